// round 4
// baseline (speedup 1.0000x reference)
#include <cuda_runtime.h>

// metadata order: d_in[0]=x (float32, 4*4096*4096), d_in[1]=coeffs (float32, 3),
//                 d_in[2]=importance (float32, 4096). output float32, 67108864 elems.

#define D 4096
#define KEEP 2048
#define N4 16777216                 // 4*4096*4096 / 4 float4
#define NBLK 740                    // 148 SMs * 5 resident blocks
#define BLOCK 256
#define GTOT (NBLK * BLOCK)         // 189440 = 1024 * 185  (multiple of D/4!)
#define FULL_ITERS 88               // guaranteed per-thread full iterations
// check: worst thread gtid=GTOT-1: (N4 - (GTOT-1)) / GTOT = 87.56 -> 88 iters. ok.

__device__ float4  g_mask4[D / 4];  // channel mask as float {0,1}
__device__ unsigned g_barrier;      // monotone ticket counter (zero-init)

__global__ void __launch_bounds__(BLOCK, 5) fused_kernel(
    const float*  __restrict__ imp,
    const float*  __restrict__ coeffs,
    const float4* __restrict__ x,
    float4*       __restrict__ out)
{
    const int tloc = threadIdx.x;
    const int gtid = blockIdx.x * BLOCK + tloc;

    // ---------------- Phase 1: exact top-k mask, one warp per channel -------
    // rank(d) = #{j: imp[j] > imp[d]} + #{j<d: imp[j]==imp[d]}  (lax.top_k
    // tie-break: lower index wins). Kept iff rank < KEEP.
    {
        const int gw   = gtid >> 5;      // global warp id; 5920 warps, 4096 used
        const int lane = tloc & 31;
        if (gw < D) {
            const float v = __ldg(&imp[gw]);
            int rank = 0;
            #pragma unroll 8
            for (int j = lane; j < D; j += 32) {
                float w = __ldg(&imp[j]);        // 16 KB array: L1/L2 hits
                rank += (w > v) || (w == v && j < gw);
            }
            #pragma unroll
            for (int off = 16; off > 0; off >>= 1)
                rank += __shfl_xor_sync(0xFFFFFFFFu, rank, off);
            if (lane == 0)
                reinterpret_cast<float*>(g_mask4)[gw] = (rank < KEEP) ? 1.0f : 0.0f;
        }
    }

    // ---------------- Device-wide software barrier --------------------------
    // All NBLK blocks are guaranteed co-resident (launch_bounds minBlocks=5,
    // grid = 148*5). Ticket counter is monotone across graph replays; it is a
    // multiple of NBLK at every kernel boundary, so targets are consistent.
    __threadfence();
    __syncthreads();
    if (tloc == 0) {
        unsigned ticket = atomicAdd(&g_barrier, 1u);
        unsigned target = (ticket / NBLK + 1u) * NBLK;
        unsigned cur;
        do {
            asm volatile("ld.acquire.gpu.u32 %0, [%1];"
                         : "=r"(cur) : "l"(&g_barrier));
            if (cur < target) __nanosleep(32);
        } while (cur < target);
    }
    __syncthreads();

    // ---------------- Phase 2: streaming polynomial -------------------------
    const float c0 = __ldg(&coeffs[0]);
    const float c1 = __ldg(&coeffs[1]);
    const float c2 = __ldg(&coeffs[2]);

    // GTOT is a multiple of D/4, so this thread's channel residue never
    // changes across the grid-stride loop: ONE mask load for the whole kernel.
    const float4 m = __ldcg(&g_mask4[gtid & (D / 4 - 1)]);
    const bool mx = (m.x != 0.0f), my = (m.y != 0.0f),
               mz = (m.z != 0.0f), mw = (m.w != 0.0f);

    const float4* xp = x   + gtid;
    float4*       op = out + gtid;

    #pragma unroll 1
    for (int b = 0; b < FULL_ITERS / 4; ++b) {          // 22 branch-free batches
        float4 xv[4];
        #pragma unroll
        for (int k = 0; k < 4; ++k)
            xv[k] = __ldcs(xp + k * GTOT);              // streaming, bypass L1
        #pragma unroll
        for (int k = 0; k < 4; ++k) {
            float4 xk = xv[k];
            float4 ov;
            ov.x = mx ? xk.x * fmaf(xk.x, fmaf(xk.x, c2, c1), c0) : xk.x;
            ov.y = my ? xk.y * fmaf(xk.y, fmaf(xk.y, c2, c1), c0) : xk.y;
            ov.z = mz ? xk.z * fmaf(xk.z, fmaf(xk.z, c2, c1), c0) : xk.z;
            ov.w = mw ? xk.w * fmaf(xk.w, fmaf(xk.w, c2, c1), c0) : xk.w;
            __stcs(op + k * GTOT, ov);                  // streaming store
        }
        xp += 4 * GTOT;
        op += 4 * GTOT;
    }

    // tail: at most one extra vector per thread (threads with gtid < 106496)
    {
        long i = (long)gtid + (long)FULL_ITERS * GTOT;
        if (i < N4) {
            float4 xk = __ldcs(x + i);
            float4 ov;
            ov.x = mx ? xk.x * fmaf(xk.x, fmaf(xk.x, c2, c1), c0) : xk.x;
            ov.y = my ? xk.y * fmaf(xk.y, fmaf(xk.y, c2, c1), c0) : xk.y;
            ov.z = mz ? xk.z * fmaf(xk.z, fmaf(xk.z, c2, c1), c0) : xk.z;
            ov.w = mw ? xk.w * fmaf(xk.w, fmaf(xk.w, c2, c1), c0) : xk.w;
            __stcs(out + i, ov);
        }
    }
}

extern "C" void kernel_launch(void* const* d_in, const int* in_sizes, int n_in,
                              void* d_out, int out_size) {
    const float* x      = (const float*)d_in[0];
    const float* coeffs = (const float*)d_in[1];
    const float* imp    = (const float*)d_in[2];
    float* out          = (float*)d_out;

    fused_kernel<<<NBLK, BLOCK>>>(imp, coeffs, (const float4*)x, (float4*)out);
}

// round 5
// speedup vs baseline: 1.1209x; 1.1209x over previous
#include <cuda_runtime.h>

// metadata order: d_in[0]=x (float32, 4*4096*4096), d_in[1]=coeffs (float32, 3),
//                 d_in[2]=importance (float32, 4096). output float32, 67108864 elems.

#define D 4096
#define KEEP 2048
#define N_TOTAL (4 * 4096 * 4096)
#define N4 (N_TOTAL / 4)            // 16,777,216 float4
#define VEC_PER_THREAD 4
#define POLY_BLOCK 256
#define POLY_GRID (N4 / (POLY_BLOCK * VEC_PER_THREAD))  // 16384

// scratch: channel mask as float {0,1}, float4-aligned device global
__device__ float4 g_mask4[D / 4];

// ---------------------------------------------------------------------------
// Kernel 1: exact top-k channel mask, one WARP per channel.
// rank(d) = #{j: imp[j] > imp[d]} + #{j < d: imp[j] == imp[d]}  (lax.top_k
// tie-break: lower index wins). Kept iff rank < KEEP.
// 128 blocks x 1024 threads = 4096 warps; one smem stage of imp per block.
// ---------------------------------------------------------------------------
__global__ void __launch_bounds__(1024) mask_kernel(const float* __restrict__ imp) {
    __shared__ float s[D];
    #pragma unroll
    for (int j = threadIdx.x; j < D; j += 1024)
        s[j] = imp[j];
    __syncthreads();

    const int d    = (blockIdx.x * 1024 + threadIdx.x) >> 5;  // 0..4095
    const int lane = threadIdx.x & 31;
    const float v  = s[d];

    int rank = 0;
    #pragma unroll 8
    for (int j = lane; j < D; j += 32) {
        float w = s[j];
        rank += (w > v) || (w == v && j < d);
    }
    #pragma unroll
    for (int off = 16; off > 0; off >>= 1)
        rank += __shfl_xor_sync(0xFFFFFFFFu, rank, off);

    if (lane == 0)
        reinterpret_cast<float*>(g_mask4)[d] = (rank < KEEP) ? 1.0f : 0.0f;
}

// ---------------------------------------------------------------------------
// Kernel 2: streaming polynomial.
//   kept:     y = x*(c0 + x*(c1 + x*c2))
//   dropped:  y = x
// Branch-free via per-channel effective coefficients:
//   s2 = m*c2, s1 = m*c1, s0 = 1 + m*(c0-1)   (m in {0,1})
//   y  = x*(s0 + x*(s1 + x*s2))
// 4 float4 per thread, front-batched streaming loads, streaming stores.
// ---------------------------------------------------------------------------
__global__ void __launch_bounds__(POLY_BLOCK) poly_kernel(
    const float4* __restrict__ x,
    float4* __restrict__ out,
    const float* __restrict__ coeffs)
{
    const float c0m1 = coeffs[0] - 1.0f;
    const float c1   = coeffs[1];
    const float c2   = coeffs[2];

    const int base = blockIdx.x * (POLY_BLOCK * VEC_PER_THREAD) + threadIdx.x;

    float4 xv[VEC_PER_THREAD];
    float4 mv[VEC_PER_THREAD];

    // front-batch all loads for max MLP
    #pragma unroll
    for (int k = 0; k < VEC_PER_THREAD; ++k) {
        int i = base + k * POLY_BLOCK;
        xv[k] = __ldcs(&x[i]);                      // stream, bypass L1
        mv[k] = __ldg(&g_mask4[i & (D / 4 - 1)]);   // hot 16 KB, L1-resident
    }

    #pragma unroll
    for (int k = 0; k < VEC_PER_THREAD; ++k) {
        float4 xk = xv[k];
        float4 mk = mv[k];
        float4 ov;
        {
            float s0 = fmaf(mk.x, c0m1, 1.0f), s1 = mk.x * c1, s2 = mk.x * c2;
            ov.x = xk.x * fmaf(xk.x, fmaf(xk.x, s2, s1), s0);
        }
        {
            float s0 = fmaf(mk.y, c0m1, 1.0f), s1 = mk.y * c1, s2 = mk.y * c2;
            ov.y = xk.y * fmaf(xk.y, fmaf(xk.y, s2, s1), s0);
        }
        {
            float s0 = fmaf(mk.z, c0m1, 1.0f), s1 = mk.z * c1, s2 = mk.z * c2;
            ov.z = xk.z * fmaf(xk.z, fmaf(xk.z, s2, s1), s0);
        }
        {
            float s0 = fmaf(mk.w, c0m1, 1.0f), s1 = mk.w * c1, s2 = mk.w * c2;
            ov.w = xk.w * fmaf(xk.w, fmaf(xk.w, s2, s1), s0);
        }
        __stcs(&out[base + k * POLY_BLOCK], ov);    // streaming store
    }
}

extern "C" void kernel_launch(void* const* d_in, const int* in_sizes, int n_in,
                              void* d_out, int out_size) {
    const float* x      = (const float*)d_in[0];
    const float* coeffs = (const float*)d_in[1];
    const float* imp    = (const float*)d_in[2];
    float* out          = (float*)d_out;

    mask_kernel<<<128, 1024>>>(imp);
    poly_kernel<<<POLY_GRID, POLY_BLOCK>>>((const float4*)x, (float4*)out, coeffs);
}